// round 1
// baseline (speedup 1.0000x reference)
#include <cuda_runtime.h>
#include <stdint.h>

// Problem constants (match reference)
#define B_IMG   64
#define M_GT    100
#define N_PROP  4000
#define K_TOT   (N_PROP + M_GT)   // 4100
#define SORT_N  8192              // next pow2 >= K_TOT
#define NUM_CLASSES 80
#define BATCH   512
#define NFG_TGT 128
#define THREADS 1024

struct Smem {
    float4 gtb[M_GT];                  // gt boxes (x1,y1,x2,y2)
    float  gta[M_GT];                  // gt areas
    float  mval[K_TOT];                // matched_vals
    int    midx[K_TOT];                // matched_idxs
    int    cnt_fg;
    unsigned long long skey[SORT_N];   // (fg<<63)|(pri_bits<<32)|k, pad=0
};

extern __shared__ unsigned char smem_raw[];

__global__ __launch_bounds__(THREADS, 1)
void roiheads_kernel(const float* __restrict__ gt_boxes,
                     const float* __restrict__ prop_boxes,
                     const int*   __restrict__ gt_classes,
                     const float* __restrict__ rand_pri,
                     float* __restrict__ out,
                     int sec_stride)   // out_size / 5
{
    Smem* s = reinterpret_cast<Smem*>(smem_raw);
    const int b   = blockIdx.x;
    const int tid = threadIdx.x;

    const float* gtb  = gt_boxes   + (size_t)b * M_GT * 4;
    const float* ppb  = prop_boxes + (size_t)b * N_PROP * 4;
    const float* pri  = rand_pri   + (size_t)b * K_TOT;
    const int*   gcls = gt_classes + (size_t)b * M_GT;

    // ---- load gt boxes + areas into SMEM ----
    for (int m = tid; m < M_GT; m += THREADS) {
        float4 bx = *reinterpret_cast<const float4*>(gtb + m * 4);
        s->gtb[m] = bx;
        s->gta[m] = (bx.z - bx.x) * (bx.w - bx.y);
    }
    if (tid == 0) s->cnt_fg = 0;
    __syncthreads();

    // ---- IoU matching + sort-key construction ----
    int local_fg = 0;
    for (int k = tid; k < SORT_N; k += THREADS) {
        if (k < K_TOT) {
            float4 bx = (k < N_PROP)
                ? *reinterpret_cast<const float4*>(ppb + k * 4)
                : s->gtb[k - N_PROP];
            float area_b = (bx.z - bx.x) * (bx.w - bx.y);
            float best = -1.0f;
            int   bi   = 0;
            #pragma unroll 5
            for (int m = 0; m < M_GT; m++) {
                float4 g = s->gtb[m];
                float w = fminf(g.z, bx.z) - fmaxf(g.x, bx.x);
                float h = fminf(g.w, bx.w) - fmaxf(g.y, bx.y);
                w = fmaxf(w, 0.0f);
                h = fmaxf(h, 0.0f);
                float inter = w * h;
                float iou = (inter > 0.0f)
                    ? inter / (s->gta[m] + area_b - inter)
                    : 0.0f;
                if (iou > best) { best = iou; bi = m; }   // first-max, matches argmax
            }
            s->mval[k] = best;
            s->midx[k] = bi;
            bool fg = (best >= 0.5f);
            local_fg += fg ? 1 : 0;
            unsigned int key32 = __float_as_uint(pri[k]);   // pri in [0,1): monotone as uint
            if (fg) key32 |= 0x80000000u;
            s->skey[k] = ((unsigned long long)key32 << 32) | (unsigned int)k;
        } else {
            s->skey[k] = 0ull;   // pad: sorts below everything real
        }
    }
    // reduce fg count (warp-reduce + one atomic per warp)
    #pragma unroll
    for (int o = 16; o; o >>= 1)
        local_fg += __shfl_down_sync(0xffffffffu, local_fg, o);
    if ((tid & 31) == 0 && local_fg) atomicAdd(&s->cnt_fg, local_fg);
    __syncthreads();

    // ---- bitonic sort, descending on composite key ----
    // Descending sort with index-in-low-bits reproduces jnp argsort(...)[::-1]
    // tie-breaking (larger original index first on equal priority).
    for (int kk = 2; kk <= SORT_N; kk <<= 1) {
        for (int j = kk >> 1; j > 0; j >>= 1) {
            #pragma unroll
            for (int i0 = 0; i0 < SORT_N; i0 += THREADS) {
                int i = i0 + tid;
                int ixj = i ^ j;
                if (ixj > i) {
                    unsigned long long a = s->skey[i];
                    unsigned long long c = s->skey[ixj];
                    bool upblock = ((i & kk) == 0);
                    if (upblock ? (a < c) : (a > c)) {
                        s->skey[i]   = c;
                        s->skey[ixj] = a;
                    }
                }
            }
            __syncthreads();
        }
    }

    // ---- emit sampled outputs ----
    const int cfg    = s->cnt_fg;
    const int num_fg = min(NFG_TGT, cfg);
    const int cbg    = K_TOT - cfg;
    const int num_bg = min(BATCH - num_fg, cbg);
    const int nvalid = num_fg + num_bg;

    float* o_iou = out + 0 * (size_t)sec_stride + (size_t)b * BATCH;
    float* o_idx = out + 1 * (size_t)sec_stride + (size_t)b * BATCH;
    float* o_cls = out + 2 * (size_t)sec_stride + (size_t)b * BATCH;
    float* o_gt  = out + 3 * (size_t)sec_stride + (size_t)b * BATCH;
    float* o_val = out + 4 * (size_t)sec_stride + (size_t)b * BATCH;

    for (int p = tid; p < BATCH; p += THREADS) {
        float viou = 0.0f, vidx = -1.0f, vcls = -1.0f, vgt = -1.0f, vval = 0.0f;
        if (p < nvalid) {
            // fg block occupies sorted positions [0, cfg); bg starts at cfg
            int pos = (p < num_fg) ? p : (cfg + (p - num_fg));
            unsigned long long key = s->skey[pos];
            int  idx = (int)(key & 0xffffffffull);
            bool fg  = (key >> 63) & 1ull;
            viou = s->mval[idx];
            vidx = (float)idx;
            int mi = s->midx[idx];
            vcls = fg ? (float)gcls[mi] : (float)NUM_CLASSES;
            vgt  = (float)mi;
            vval = 1.0f;
        }
        o_iou[p] = viou;
        o_idx[p] = vidx;
        o_cls[p] = vcls;
        o_gt[p]  = vgt;
        o_val[p] = vval;
    }
}

extern "C" void kernel_launch(void* const* d_in, const int* in_sizes, int n_in,
                              void* d_out, int out_size) {
    const float* gt_boxes   = (const float*)d_in[0];
    const float* prop_boxes = (const float*)d_in[1];
    const int*   gt_classes = (const int*)d_in[2];
    const float* rand_pri   = (const float*)d_in[3];
    float* out = (float*)d_out;

    int sec_stride = out_size / 5;   // 5 concatenated output sections

    static bool attr_set = false;    // host-side attribute, not work-gating
    if (!attr_set) {
        cudaFuncSetAttribute(roiheads_kernel,
                             cudaFuncAttributeMaxDynamicSharedMemorySize,
                             (int)sizeof(Smem));
        attr_set = true;
    }
    roiheads_kernel<<<B_IMG, THREADS, sizeof(Smem)>>>(
        gt_boxes, prop_boxes, gt_classes, rand_pri, out, sec_stride);
}

// round 2
// speedup vs baseline: 1.6589x; 1.6589x over previous
#include <cuda_runtime.h>
#include <stdint.h>

// Problem constants (match reference)
#define B_IMG   64
#define M_GT    100
#define N_PROP  4000
#define K_TOT   (N_PROP + M_GT)   // 4100
#define NUM_CLASSES 80
#define BATCH   512
#define NFG_TGT 128
#define THREADS 1024
#define HBINS   1024
#define CAP     2048              // candidate capacity (pow2)
#define NEED_FG 128
#define NEED_BG 512

typedef unsigned long long ull;

struct Smem {
    float4 gtb[M_GT];
    float  gta[M_GT];
    float  mval[K_TOT];
    int    midx[K_TOT];
    ull    keys[K_TOT];      // (fg<<63)|(pri_bits<<32)|k
    ull    cand[CAP];
    int    hist_fg[HBINS];
    int    hist_bg[HBINS];
    int    t_fg, t_bg, ncand;
};

extern __shared__ unsigned char smem_raw[];

__global__ __launch_bounds__(THREADS, 1)
void roiheads_kernel(const float* __restrict__ gt_boxes,
                     const float* __restrict__ prop_boxes,
                     const int*   __restrict__ gt_classes,
                     const float* __restrict__ rand_pri,
                     float* __restrict__ out,
                     int sec_stride)
{
    Smem* s = reinterpret_cast<Smem*>(smem_raw);
    const int b   = blockIdx.x;
    const int tid = threadIdx.x;

    const float* gtb  = gt_boxes   + (size_t)b * M_GT * 4;
    const float* ppb  = prop_boxes + (size_t)b * N_PROP * 4;
    const float* pri  = rand_pri   + (size_t)b * K_TOT;
    const int*   gcls = gt_classes + (size_t)b * M_GT;

    // ---- init: gt boxes, zero hists + cand pad ----
    if (tid < M_GT) {
        float4 bx = *reinterpret_cast<const float4*>(gtb + tid * 4);
        s->gtb[tid] = bx;
        s->gta[tid] = (bx.z - bx.x) * (bx.w - bx.y);
    }
    s->hist_fg[tid] = 0;
    s->hist_bg[tid] = 0;
    s->cand[tid] = 0ull;
    s->cand[tid + 1024] = 0ull;
    if (tid == 0) { s->t_fg = 0; s->t_bg = 0; s->ncand = 0; }
    __syncthreads();

    // ---- IoU matching + key build + priority histograms ----
    for (int k = tid; k < K_TOT; k += THREADS) {
        float4 bx = (k < N_PROP)
            ? *reinterpret_cast<const float4*>(ppb + k * 4)
            : s->gtb[k - N_PROP];
        float area_b = (bx.z - bx.x) * (bx.w - bx.y);
        float best = -1.0f;
        int   bi   = 0;
        #pragma unroll 5
        for (int m = 0; m < M_GT; m++) {
            float4 g = s->gtb[m];
            float w = fminf(g.z, bx.z) - fmaxf(g.x, bx.x);
            float h = fminf(g.w, bx.w) - fmaxf(g.y, bx.y);
            w = fmaxf(w, 0.0f);
            h = fmaxf(h, 0.0f);
            float inter = w * h;
            float iou = (inter > 0.0f)
                ? inter / (s->gta[m] + area_b - inter)
                : 0.0f;
            if (iou > best) { best = iou; bi = m; }   // first-max == argmax
        }
        s->mval[k] = best;
        s->midx[k] = bi;
        bool fg = (best >= 0.5f);
        float p = pri[k];                         // [0,1)
        int bin = min(HBINS - 1, (int)(p * (float)HBINS));
        atomicAdd(fg ? &s->hist_fg[bin] : &s->hist_bg[bin], 1);
        unsigned int key32 = __float_as_uint(p);  // monotone, < 2^31
        if (fg) key32 |= 0x80000000u;
        s->keys[k] = ((ull)key32 << 32) | (unsigned int)k;
    }
    __syncthreads();

    // ---- suffix scan (sfx[t] = count of elems in bins >= t) ----
    #pragma unroll
    for (int step = 1; step < HBINS; step <<= 1) {
        int vf = s->hist_fg[tid] + ((tid + step < HBINS) ? s->hist_fg[tid + step] : 0);
        int vb = s->hist_bg[tid] + ((tid + step < HBINS) ? s->hist_bg[tid + step] : 0);
        __syncthreads();
        s->hist_fg[tid] = vf;
        s->hist_bg[tid] = vb;
        __syncthreads();
    }

    // ---- find bin cutoffs (unique crossing since sfx non-increasing) ----
    {
        int sf  = s->hist_fg[tid];
        int sfn = (tid < HBINS - 1) ? s->hist_fg[tid + 1] : 0;
        if (sf >= NEED_FG && sfn < NEED_FG) s->t_fg = tid;
        int sb  = s->hist_bg[tid];
        int sbn = (tid < HBINS - 1) ? s->hist_bg[tid + 1] : 0;
        if (sb >= NEED_BG && sbn < NEED_BG) s->t_bg = tid;
    }
    __syncthreads();

    // ---- gather candidates (superset of reference's selected top-k) ----
    const int tfg = s->t_fg, tbg = s->t_bg;
    for (int k = tid; k < K_TOT; k += THREADS) {
        ull key = s->keys[k];
        bool fg = (key >> 63) != 0ull;
        float p = __uint_as_float((unsigned int)(key >> 32) & 0x7fffffffu);
        int bin = min(HBINS - 1, (int)(p * (float)HBINS));
        if (bin >= (fg ? tfg : tbg)) {
            int pos = atomicAdd(&s->ncand, 1);
            if (pos < CAP) s->cand[pos] = key;
        }
    }
    __syncthreads();

    const int nc = s->ncand;
    const int nsort = (nc <= 1024) ? 1024 : CAP;

    // ---- bitonic sort (descending) over nsort candidates ----
    for (int kk = 2; kk <= nsort; kk <<= 1) {
        for (int j = kk >> 1; j > 0; j >>= 1) {
            for (int i0 = 0; i0 < nsort; i0 += THREADS) {
                int i = i0 + tid;
                int ixj = i ^ j;
                if (ixj > i) {
                    ull a = s->cand[i];
                    ull c = s->cand[ixj];
                    bool upblock = ((i & kk) == 0);
                    if (upblock ? (a < c) : (a > c)) {
                        s->cand[i]   = c;
                        s->cand[ixj] = a;
                    }
                }
            }
            __syncthreads();
        }
    }

    // ---- emit sampled outputs ----
    const int cfg     = s->hist_fg[0];        // total fg
    const int cand_fg = s->hist_fg[tfg];      // fg candidates (sorted block length)
    const int num_fg  = min(NFG_TGT, cfg);
    const int cbg     = K_TOT - cfg;
    const int num_bg  = min(BATCH - num_fg, cbg);
    const int nvalid  = num_fg + num_bg;

    float* o_iou = out + 0 * (size_t)sec_stride + (size_t)b * BATCH;
    float* o_idx = out + 1 * (size_t)sec_stride + (size_t)b * BATCH;
    float* o_cls = out + 2 * (size_t)sec_stride + (size_t)b * BATCH;
    float* o_gt  = out + 3 * (size_t)sec_stride + (size_t)b * BATCH;
    float* o_val = out + 4 * (size_t)sec_stride + (size_t)b * BATCH;

    for (int p = tid; p < BATCH; p += THREADS) {
        float viou = 0.0f, vidx = -1.0f, vcls = -1.0f, vgt = -1.0f, vval = 0.0f;
        if (p < nvalid) {
            int pos = (p < num_fg) ? p : (cand_fg + (p - num_fg));
            ull key = s->cand[pos];
            int  idx = (int)(key & 0xffffffffull);
            bool fg  = (key >> 63) != 0ull;
            viou = s->mval[idx];
            vidx = (float)idx;
            int mi = s->midx[idx];
            vcls = fg ? (float)gcls[mi] : (float)NUM_CLASSES;
            vgt  = (float)mi;
            vval = 1.0f;
        }
        o_iou[p] = viou;
        o_idx[p] = vidx;
        o_cls[p] = vcls;
        o_gt[p]  = vgt;
        o_val[p] = vval;
    }
}

extern "C" void kernel_launch(void* const* d_in, const int* in_sizes, int n_in,
                              void* d_out, int out_size) {
    const float* gt_boxes   = (const float*)d_in[0];
    const float* prop_boxes = (const float*)d_in[1];
    const int*   gt_classes = (const int*)d_in[2];
    const float* rand_pri   = (const float*)d_in[3];
    float* out = (float*)d_out;

    int sec_stride = out_size / 5;

    static bool attr_set = false;
    if (!attr_set) {
        cudaFuncSetAttribute(roiheads_kernel,
                             cudaFuncAttributeMaxDynamicSharedMemorySize,
                             (int)sizeof(Smem));
        attr_set = true;
    }
    roiheads_kernel<<<B_IMG, THREADS, sizeof(Smem)>>>(
        gt_boxes, prop_boxes, gt_classes, rand_pri, out, sec_stride);
}

// round 4
// speedup vs baseline: 3.6349x; 2.1911x over previous
#include <cuda_runtime.h>
#include <stdint.h>

#define B_IMG   64
#define M_GT    100
#define N_PROP  4000
#define K_TOT   (N_PROP + M_GT)   // 4100
#define NUM_CLASSES 80
#define BATCH   512
#define NFG_TGT 128
#define HBINS   1024
#define CAP     2048
#define NEED_FG 128
#define NEED_BG 512

#define T1      512               // kernel1 threads
#define S_SLICES 9                // ceil(4100/512)
#define T2      1024              // kernel2 threads

typedef unsigned long long ull;

// __device__ scratch (allocation-free rule)
__device__ ull   g_keys[B_IMG * K_TOT];
__device__ float g_mval[B_IMG * K_TOT];
__device__ int   g_midx[B_IMG * K_TOT];
__device__ int   g_hist[B_IMG * S_SLICES * 2 * HBINS];  // [img][slice][fg|bg][bin]

// ================= Kernel 1: IoU matching + keys + per-slice histograms ==========
__global__ __launch_bounds__(T1)
void match_kernel(const float* __restrict__ gt_boxes,
                  const float* __restrict__ prop_boxes,
                  const float* __restrict__ rand_pri)
{
    __shared__ float4 sgtb[M_GT];
    __shared__ float  sgta[M_GT];
    __shared__ int    shist[2 * HBINS];

    const int c     = blockIdx.x;
    const int img   = c / S_SLICES;
    const int slice = c % S_SLICES;
    const int tid   = threadIdx.x;

    const float* gtb = gt_boxes + (size_t)img * M_GT * 4;

    if (tid < M_GT) {
        float4 bx = *reinterpret_cast<const float4*>(gtb + tid * 4);
        sgtb[tid] = bx;
        sgta[tid] = (bx.z - bx.x) * (bx.w - bx.y);
    }
    for (int i = tid; i < 2 * HBINS; i += T1) shist[i] = 0;
    __syncthreads();

    const int k = slice * T1 + tid;
    if (k < K_TOT) {
        float4 bx;
        if (k < N_PROP)
            bx = *reinterpret_cast<const float4*>(prop_boxes + ((size_t)img * N_PROP + k) * 4);
        else
            bx = sgtb[k - N_PROP];
        const float area_b = (bx.z - bx.x) * (bx.w - bx.y);

        // division-free argmax: track (inter, union) of best; compare via cross-mult
        float best_i = -1.0f, best_u = 1.0f;
        int   bi = 0;
        #pragma unroll 4
        for (int m = 0; m < M_GT; m++) {
            float4 g = sgtb[m];
            float w = fminf(g.z, bx.z) - fmaxf(g.x, bx.x);
            float h = fminf(g.w, bx.w) - fmaxf(g.y, bx.y);
            w = fmaxf(w, 0.0f);
            h = fmaxf(h, 0.0f);
            float inter = w * h;                        // >= 0 (clamped)
            float uni   = (sgta[m] + area_b) - inter;   // > 0
            // iou_m > best  <=>  inter*best_u > best_i*uni
            if (inter * best_u > best_i * uni) {
                best_i = inter; best_u = uni; bi = m;   // first-max preserved
            }
        }
        float mval = best_i / best_u;       // one exact IEEE divide
        bool  fg   = (mval >= 0.5f);

        const size_t gk = (size_t)img * K_TOT + k;
        g_mval[gk] = mval;
        g_midx[gk] = bi;

        float p = rand_pri[gk];             // [0,1)
        unsigned int key32 = __float_as_uint(p);
        if (fg) key32 |= 0x80000000u;
        g_keys[gk] = ((ull)key32 << 32) | (unsigned int)k;

        int bin = min(HBINS - 1, (int)(p * (float)HBINS));
        atomicAdd(&shist[(fg ? 0 : HBINS) + bin], 1);
    }
    __syncthreads();

    int* gh = g_hist + ((size_t)img * S_SLICES + slice) * 2 * HBINS;
    for (int i = tid; i < 2 * HBINS; i += T1) gh[i] = shist[i];
}

// ================= Kernel 2: scan + select + sort + emit =========================
__global__ __launch_bounds__(T2)
void sample_kernel(const int* __restrict__ gt_classes,
                   float* __restrict__ out,
                   int sec_stride)
{
    __shared__ int hfg[HBINS];
    __shared__ int hbg[HBINS];
    __shared__ ull cand[CAP];
    __shared__ int t_fg, t_bg, ncand;

    const int b   = blockIdx.x;
    const int tid = threadIdx.x;

    // sum per-slice histograms
    int vf = 0, vb = 0;
    #pragma unroll
    for (int sl = 0; sl < S_SLICES; sl++) {
        const int* gh = g_hist + ((size_t)b * S_SLICES + sl) * 2 * HBINS;
        vf += gh[tid];
        vb += gh[HBINS + tid];
    }
    hfg[tid] = vf;
    hbg[tid] = vb;
    cand[tid] = 0ull;
    cand[tid + 1024] = 0ull;
    if (tid == 0) { t_fg = 0; t_bg = 0; ncand = 0; }
    __syncthreads();

    // suffix scan: hist[t] := count of elems with bin >= t
    #pragma unroll
    for (int step = 1; step < HBINS; step <<= 1) {
        int nf = hfg[tid] + ((tid + step < HBINS) ? hfg[tid + step] : 0);
        int nb = hbg[tid] + ((tid + step < HBINS) ? hbg[tid + step] : 0);
        __syncthreads();
        hfg[tid] = nf;
        hbg[tid] = nb;
        __syncthreads();
    }

    // cutoffs (unique crossing of non-increasing suffix)
    {
        int sf = hfg[tid], sfn = (tid < HBINS - 1) ? hfg[tid + 1] : 0;
        if (sf >= NEED_FG && sfn < NEED_FG) t_fg = tid;
        int sb = hbg[tid], sbn = (tid < HBINS - 1) ? hbg[tid + 1] : 0;
        if (sb >= NEED_BG && sbn < NEED_BG) t_bg = tid;
    }
    __syncthreads();

    // gather candidates (superset of reference top-k per group)
    const int tfg = t_fg, tbg = t_bg;
    const ull* keys = g_keys + (size_t)b * K_TOT;
    for (int k = tid; k < K_TOT; k += T2) {
        ull key = keys[k];
        bool fg = (key >> 63) != 0ull;
        float p = __uint_as_float((unsigned int)(key >> 32) & 0x7fffffffu);
        int bin = min(HBINS - 1, (int)(p * (float)HBINS));
        if (bin >= (fg ? tfg : tbg)) {
            int pos = atomicAdd(&ncand, 1);
            if (pos < CAP) cand[pos] = key;
        }
    }
    __syncthreads();

    const int nc = ncand;
    const int nsort = (nc <= 1024) ? 1024 : CAP;

    // bitonic sort, descending on composite key
    for (int kk = 2; kk <= nsort; kk <<= 1) {
        for (int j = kk >> 1; j > 0; j >>= 1) {
            for (int i0 = 0; i0 < nsort; i0 += T2) {
                int i = i0 + tid;
                int ixj = i ^ j;
                if (ixj > i) {
                    ull a = cand[i];
                    ull c2 = cand[ixj];
                    bool up = ((i & kk) == 0);
                    if (up ? (a < c2) : (a > c2)) {
                        cand[i]   = c2;
                        cand[ixj] = a;
                    }
                }
            }
            __syncthreads();
        }
    }

    // emit
    const int cfg     = hfg[0];
    const int cand_fg = hfg[tfg];
    const int num_fg  = min(NFG_TGT, cfg);
    const int cbg     = K_TOT - cfg;
    const int num_bg  = min(BATCH - num_fg, cbg);
    const int nvalid  = num_fg + num_bg;

    const int*   gcls = gt_classes + (size_t)b * M_GT;
    const float* mv   = g_mval + (size_t)b * K_TOT;
    const int*   mi_g = g_midx + (size_t)b * K_TOT;

    float* o_iou = out + 0 * (size_t)sec_stride + (size_t)b * BATCH;
    float* o_idx = out + 1 * (size_t)sec_stride + (size_t)b * BATCH;
    float* o_cls = out + 2 * (size_t)sec_stride + (size_t)b * BATCH;
    float* o_gt  = out + 3 * (size_t)sec_stride + (size_t)b * BATCH;
    float* o_val = out + 4 * (size_t)sec_stride + (size_t)b * BATCH;

    for (int p = tid; p < BATCH; p += T2) {
        float viou = 0.0f, vidx = -1.0f, vcls = -1.0f, vgt = -1.0f, vval = 0.0f;
        if (p < nvalid) {
            int pos = (p < num_fg) ? p : (cand_fg + (p - num_fg));
            ull key = cand[pos];
            int  idx = (int)(key & 0xffffffffull);
            bool fg  = (key >> 63) != 0ull;
            viou = mv[idx];
            vidx = (float)idx;
            int mi = mi_g[idx];
            vcls = fg ? (float)gcls[mi] : (float)NUM_CLASSES;
            vgt  = (float)mi;
            vval = 1.0f;
        }
        o_iou[p] = viou;
        o_idx[p] = vidx;
        o_cls[p] = vcls;
        o_gt[p]  = vgt;
        o_val[p] = vval;
    }
}

extern "C" void kernel_launch(void* const* d_in, const int* in_sizes, int n_in,
                              void* d_out, int out_size) {
    const float* gt_boxes   = (const float*)d_in[0];
    const float* prop_boxes = (const float*)d_in[1];
    const int*   gt_classes = (const int*)d_in[2];
    const float* rand_pri   = (const float*)d_in[3];
    float* out = (float*)d_out;

    int sec_stride = out_size / 5;

    match_kernel<<<B_IMG * S_SLICES, T1>>>(gt_boxes, prop_boxes, rand_pri);
    sample_kernel<<<B_IMG, T2>>>(gt_classes, out, sec_stride);
}